// round 14
// baseline (speedup 1.0000x reference)
#include <cuda_runtime.h>

#define BB 16
#define NN 4096
#define SS 512
#define NSAMP 32
#define PPOS (BB*SS*NSAMP)   // 262144 positions
#define NGRP (BB*SS)         // 8192 (b,s) groups
#define NPERS 296            // persistent grid (2 CTAs x 148 SMs)
#define TXS 136              // mlp3 padded tile row stride
#define TAS 264              // fused12 padded tile row stride (256+8)

// ---------------- device scratch ----------------
__device__ float g_feat[6*PPOS];        // grouped features [c][p]
__device__ float g_x2[64*PPOS];         // layer2 raw conv out
__device__ float2 g_pool[128*NGRP];     // {max,min} of raw layer3 per group
__device__ float g_stats[384];          // [0..127] L2 sum/sumsq, [128..383] L3
__device__ float g_gram[27*32];         // 27 moments, line-padded (864 floats)
__device__ float4 g_new[NGRP];          // centroid x,y,z,|c|^2
__device__ int   g_ctr[2];              // work-steal counters (fused12, mlp3)

// ---------------- helpers ----------------
__device__ __forceinline__ unsigned long long fma2(unsigned long long a,
                                                   unsigned long long b,
                                                   unsigned long long c) {
    unsigned long long d;
    asm("fma.rn.f32x2 %0, %1, %2, %3;" : "=l"(d) : "l"(a), "l"(b), "l"(c));
    return d;
}
__device__ __forceinline__ unsigned long long add2(unsigned long long a,
                                                   unsigned long long b) {
    unsigned long long d;
    asm("add.rn.f32x2 %0, %1, %2;" : "=l"(d) : "l"(a), "l"(b));
    return d;
}
__device__ __forceinline__ unsigned long long mul2(unsigned long long a,
                                                   unsigned long long b) {
    unsigned long long d;
    asm("mul.rn.f32x2 %0, %1, %2;" : "=l"(d) : "l"(a), "l"(b));
    return d;
}
__device__ __forceinline__ unsigned long long pack2(float lo, float hi) {
    unsigned long long d;
    asm("mov.b64 %0, {%1, %2};" : "=l"(d) : "f"(lo), "f"(hi));
    return d;
}
__device__ __forceinline__ float2 unpack2(unsigned long long v) {
    float2 r;
    asm("mov.b64 {%0, %1}, %2;" : "=f"(r.x), "=f"(r.y) : "l"(v));
    return r;
}
__device__ __forceinline__ void cp_async16(void* smem_dst, const void* gmem_src) {
    unsigned s = (unsigned)__cvta_generic_to_shared(smem_dst);
    asm volatile("cp.async.cg.shared.global [%0], [%1], 16;" :: "r"(s), "l"(gmem_src) : "memory");
}
__device__ __forceinline__ void cp_commit() { asm volatile("cp.async.commit_group;" ::: "memory"); }
__device__ __forceinline__ void cp_wait0()  { asm volatile("cp.async.wait_group 0;"  ::: "memory"); }

__device__ __forceinline__ void mma_tf32(float& c0, float& c1, float& c2, float& c3,
                                         unsigned a0, unsigned a1, unsigned a2, unsigned a3,
                                         unsigned b0, unsigned b1) {
    asm("mma.sync.aligned.m16n8k8.row.col.f32.tf32.tf32.f32 "
        "{%0,%1,%2,%3}, {%4,%5,%6,%7}, {%8,%9}, {%0,%1,%2,%3};"
        : "+f"(c0), "+f"(c1), "+f"(c2), "+f"(c3)
        : "r"(a0), "r"(a1), "r"(a2), "r"(a3), "r"(b0), "r"(b1));
}

// FPS: 1 CTA/batch, 512 threads, 8 pts/thread packed as f32x2 pairs.
__global__ __launch_bounds__(512) void fps_kernel(const float* __restrict__ xyz,
                                                  float* __restrict__ out_newxyz)
{
    extern __shared__ float sh[];
    float4* pts4 = (float4*)sh;
    float4* cbuf = (float4*)(sh + 4*NN);
    __shared__ unsigned long long wkey[2][16];
    const int b = blockIdx.x, t = threadIdx.x;
    const int lane = t & 31, wid = t >> 5;
    const float* X = xyz + b*3*NN;

    if (b == 0) {
        if (t < 384) g_stats[t] = 0.0f;
        for (int i = t; i < 27*32; i += 512) g_gram[i] = 0.0f;
        if (t == 0) { g_ctr[0] = 0; g_ctr[1] = 0; }
    }

    float xv[8], yv[8], zv[8], dist[8];
#pragma unroll
    for (int k = 0; k < 8; ++k) {
        int n = t + k*512;
        xv[k] = X[n]; yv[k] = X[NN+n]; zv[k] = X[2*NN+n];
        pts4[n] = make_float4(-xv[k], -yv[k], -zv[k], 0.0f);
        dist[k] = 1e10f;
    }
    unsigned long long px2[4], py2[4], pz2[4];
#pragma unroll
    for (int j = 0; j < 4; ++j) {
        px2[j] = pack2(xv[2*j], xv[2*j+1]);
        py2[j] = pack2(yv[2*j], yv[2*j+1]);
        pz2[j] = pack2(zv[2*j], zv[2*j+1]);
    }
    __syncthreads();

    int far = 0;
    for (int s = 0; s < SS; ++s) {
        float4 cn = pts4[far];
        if (t == 0) cbuf[s] = cn;
        unsigned long long cx2 = pack2(cn.x, cn.x);
        unsigned long long cy2 = pack2(cn.y, cn.y);
        unsigned long long cz2 = pack2(cn.z, cn.z);
#pragma unroll
        for (int j = 0; j < 4; ++j) {
            unsigned long long dx2 = add2(px2[j], cx2);
            unsigned long long dy2 = add2(py2[j], cy2);
            unsigned long long dz2 = add2(pz2[j], cz2);
            unsigned long long d2 = mul2(dx2, dx2);
            d2 = fma2(dy2, dy2, d2);
            d2 = fma2(dz2, dz2, d2);
            float2 dd = unpack2(d2);
            dist[2*j]   = fminf(dist[2*j],   dd.x);
            dist[2*j+1] = fminf(dist[2*j+1], dd.y);
        }
        float v0 = dist[0]; int q0 = 0;
        if (dist[1] > v0) { v0 = dist[1]; q0 = 1; }
        float v1 = dist[2]; int q1 = 2;
        if (dist[3] > v1) { v1 = dist[3]; q1 = 3; }
        float v2 = dist[4]; int q2 = 4;
        if (dist[5] > v2) { v2 = dist[5]; q2 = 5; }
        float v3 = dist[6]; int q3 = 6;
        if (dist[7] > v3) { v3 = dist[7]; q3 = 7; }
        if (v1 > v0) { v0 = v1; q0 = q1; }
        if (v3 > v2) { v2 = v3; q2 = q3; }
        if (v2 > v0) { v0 = v2; q0 = q2; }
        int mi = t + q0*512;

        unsigned db = __float_as_uint(v0);
        unsigned wm = __reduce_max_sync(0xFFFFFFFFu, db);
        unsigned lo = __reduce_max_sync(0xFFFFFFFFu, (db == wm) ? ~(unsigned)mi : 0u);
        if (lane == 0) wkey[s & 1][wid] = ((unsigned long long)wm << 32) | lo;
        __syncthreads();
        unsigned long long k2 = wkey[s & 1][lane & 15];
        unsigned hi = (unsigned)(k2 >> 32), l2v = (unsigned)k2;
        unsigned m2 = __reduce_max_sync(0xFFFFFFFFu, hi);
        unsigned lw = __reduce_max_sync(0xFFFFFFFFu, (hi == m2) ? l2v : 0u);
        far = (int)(~lw);
    }
    __syncthreads();
    {
        float4 cn = cbuf[t];
        float cx = -cn.x, cy = -cn.y, cz = -cn.z;
        out_newxyz[(b*3+0)*SS + t] = cx;
        out_newxyz[(b*3+1)*SS + t] = cy;
        out_newxyz[(b*3+2)*SS + t] = cz;
        float sn = fmaf(cz,cz,fmaf(cy,cy,cx*cx));
        g_new[b*SS+t] = make_float4(cx,cy,cz,sn);
    }
}

// Ball query + gather + fused 27-moment accumulation. One warp per centroid.
__global__ __launch_bounds__(256) void group_kernel(const float* __restrict__ xyz,
                                                    const float* __restrict__ pts)
{
    __shared__ int sel[8][NSAMP];
    __shared__ float red[27];
    const int lane = threadIdx.x & 31, w = threadIdx.x >> 5;
    const int tid = threadIdx.x;
    if (tid < 27) red[tid] = 0.0f;
    __syncthreads();

    const int id = blockIdx.x*8 + w;
    const int b = id >> 9;
    const float4 c4 = g_new[id];
    const float* X = xyz + b*3*NN;
    const float* Q = pts + b*3*NN;
    const float R2 = (float)(0.4*0.4);

    int cnt = 0;
    for (int base = 0; base < NN && cnt < NSAMP; base += 32) {
        int n = base + lane;
        float x = X[n], y = X[NN+n], z = X[2*NN+n];
        float sx  = fmaf(z,z,fmaf(y,y,x*x));
        float dot = fmaf(z,c4.z,fmaf(y,c4.y,x*c4.x));
        float sq  = (c4.w + sx) - 2.0f*dot;
        bool pred = (sq <= R2);
        unsigned m = __ballot_sync(0xFFFFFFFFu, pred);
        if (pred) {
            int pos = cnt + __popc(m & ((1u << lane) - 1u));
            if (pos < NSAMP) sel[w][pos] = n;
        }
        cnt += __popc(m);
    }
    __syncwarp();
    int total = cnt < NSAMP ? cnt : NSAMP;
    int idx = sel[w][lane < total ? lane : 0];

    float f[6];
    f[0] = X[idx]      - c4.x;
    f[1] = X[NN+idx]   - c4.y;
    f[2] = X[2*NN+idx] - c4.z;
    f[3] = Q[idx];
    f[4] = Q[NN+idx];
    f[5] = Q[2*NN+idx];

    int p = id*NSAMP + lane;
#pragma unroll
    for (int c = 0; c < 6; ++c) g_feat[c*PPOS + p] = f[c];

    float v[27];
#pragma unroll
    for (int c = 0; c < 6; ++c) v[c] = f[c];
    {
        int k = 6;
#pragma unroll
        for (int i = 0; i < 6; ++i)
#pragma unroll
            for (int j = i; j < 6; ++j) { v[k] = f[i]*f[j]; ++k; }
    }
#pragma unroll
    for (int off = 16; off; off >>= 1)
#pragma unroll
        for (int i = 0; i < 27; ++i)
            v[i] += __shfl_down_sync(0xFFFFFFFFu, v[i], off);
    if (lane == 0)
#pragma unroll
        for (int i = 0; i < 27; ++i) atomicAdd(&red[i], v[i]);
    __syncthreads();
    if (tid < 27) atomicAdd(&g_gram[tid*32], red[tid]);
}

// PERSISTENT fused layer1+layer2.
// Stage B: warp = 32 outputs (2 m16) x 64 positions -> halved B-fragment traffic.
__global__ __launch_bounds__(256,2) void fused12_kernel(const float* __restrict__ w0,
                                                        const float* __restrict__ b0,
                                                        const float* __restrict__ g0,
                                                        const float* __restrict__ beta0,
                                                        const float* __restrict__ w1,
                                                        const float* __restrict__ b1)
{
    extern __shared__ char smraw[];
    unsigned long long* w0d = (unsigned long long*)smraw;   // 384 ull (3072B)
    float* sab = (float*)(smraw + 3072);                    // 128 (BN1 A/B)
    float* tf  = (float*)(smraw + 3584);                    // 6 x 256 (6144B)
    float* tx  = (float*)(smraw + 9728);                    // 64 x TAS floats (67584B)
    __shared__ int s_next;
    const int tid  = threadIdx.x;
    const int lane = tid & 31, wid = tid >> 5;
    const int ob8  = wid * 8;              // stage-A output block
    const int ob32 = (wid & 1) * 32;       // stage-B output block (32 outs)
    const int pq   = (wid >> 1) * 64;      // stage-B position quarter
    const int g  = lane >> 2;
    const int t4 = lane & 3;

    // analytic BN1 (once per CTA)
    if (tid < 64) {
        const int o = tid;
        float w[6];
#pragma unroll
        for (int c = 0; c < 6; ++c) w[c] = w0[o*6+c];
        float wS = 0.0f;
#pragma unroll
        for (int c = 0; c < 6; ++c) wS = fmaf(w[c], g_gram[c*32], wS);
        float quad = 0.0f; int idx = 6;
#pragma unroll
        for (int i = 0; i < 6; ++i)
#pragma unroll
            for (int j = i; j < 6; ++j) {
                float coef = (i == j) ? 1.0f : 2.0f;
                quad = fmaf(coef * w[i] * w[j], g_gram[idx*32], quad);
                ++idx;
            }
        float bo = b0[o];
        const float invP = 1.0f / (float)PPOS;
        float m   = fmaf(wS, invP, bo);
        float Ex2 = quad*invP + 2.0f*bo*wS*invP + bo*bo;
        float A = g0[o] * rsqrtf(Ex2 - m*m + 1e-5f);
        sab[o]    = A;
        sab[64+o] = fmaf(bo - m, A, beta0[o]);
    }
    for (int i = tid; i < 384; i += 256) { float v = w0[i]; w0d[i] = pack2(v,v); }

    // W1 A-fragments: 2 m16 blocks (32 outputs), resident whole kernel.
    unsigned af[8][2][4];
#pragma unroll
    for (int kb = 0; kb < 8; ++kb)
#pragma unroll
        for (int mb = 0; mb < 2; ++mb) {
            int r = ob32 + mb*16;
            af[kb][mb][0] = __float_as_uint(w1[(r+g)*64   + kb*8 + t4]);
            af[kb][mb][1] = __float_as_uint(w1[(r+g+8)*64 + kb*8 + t4]);
            af[kb][mb][2] = __float_as_uint(w1[(r+g)*64   + kb*8 + t4 + 4]);
            af[kb][mb][3] = __float_as_uint(w1[(r+g+8)*64 + kb*8 + t4 + 4]);
        }
    const float bias0l = b1[ob32+g],    bias0h = b1[ob32+g+8];
    const float bias1l = b1[ob32+16+g], bias1h = b1[ob32+16+g+8];
    float st_s[4] = {0,0,0,0}, st_q[4] = {0,0,0,0};   // [mb*2 + lo/hi]

    int tile = blockIdx.x;
    while (tile < PPOS/256) {
        const int p0 = tile * 256;
        if (tid == 0) s_next = NPERS + atomicAdd(&g_ctr[0], 1);
        __syncthreads();
        const int next = s_next;
        for (int i = tid; i < 384; i += 256) {
            int c = i >> 6, pp = (i & 63) * 4;
            *(float4*)(tf + c*256 + pp) = *(const float4*)(g_feat + c*PPOS + p0 + pp);
        }
        __syncthreads();

        // ---- stage A: 6 -> 64 (two passes of 4 outputs; keeps regs under cap) ----
#pragma unroll
        for (int half = 0; half < 2; ++half) {
            unsigned long long a[4][4];
#pragma unroll
            for (int j = 0; j < 4; ++j)
#pragma unroll
                for (int q = 0; q < 4; ++q) a[j][q] = 0ull;
#pragma unroll
            for (int c = 0; c < 6; ++c) {
                ulonglong2 iv0 = *(const ulonglong2*)(tf + c*256 + lane*4);
                ulonglong2 iv1 = *(const ulonglong2*)(tf + c*256 + 128 + lane*4);
#pragma unroll
                for (int j = 0; j < 4; ++j) {
                    unsigned long long wv = w0d[(ob8+half*4+j)*6 + c];
                    a[j][0] = fma2(wv, iv0.x, a[j][0]);
                    a[j][1] = fma2(wv, iv0.y, a[j][1]);
                    a[j][2] = fma2(wv, iv1.x, a[j][2]);
                    a[j][3] = fma2(wv, iv1.y, a[j][3]);
                }
            }
#pragma unroll
            for (int j = 0; j < 4; ++j) {
                int row = ob8 + half*4 + j;
                float A = sab[row], Bv = sab[64+row];
#pragma unroll
                for (int s2 = 0; s2 < 2; ++s2) {
                    float2 u = unpack2(a[j][s2*2+0]);
                    float2 v = unpack2(a[j][s2*2+1]);
                    float4 o4;
                    o4.x = fmaxf(fmaf(u.x,A,Bv),0.f);
                    o4.y = fmaxf(fmaf(u.y,A,Bv),0.f);
                    o4.z = fmaxf(fmaf(v.x,A,Bv),0.f);
                    o4.w = fmaxf(fmaf(v.y,A,Bv),0.f);
                    *(float4*)(tx + row*TAS + s2*128 + lane*4) = o4;
                }
            }
        }
        __syncthreads();

        // ---- stage B: 64 -> 64 via tf32 mma (8 n8-blocks over warp's 64 pos) ----
#pragma unroll
        for (int nb = 0; nb < 8; ++nb) {
            const int pbase = pq + nb*8;
            unsigned bf0[8], bf1[8];
#pragma unroll
            for (int kb = 0; kb < 8; ++kb) {
                bf0[kb] = __float_as_uint(tx[(kb*8 + t4)*TAS     + pbase + g]);
                bf1[kb] = __float_as_uint(tx[(kb*8 + t4 + 4)*TAS + pbase + g]);
            }
            float a0 = bias0l, a1 = bias0l, a2 = bias0h, a3 = bias0h;
            float d0 = bias1l, d1 = bias1l, d2 = bias1h, d3 = bias1h;
#pragma unroll
            for (int kb = 0; kb < 8; ++kb) {
                mma_tf32(a0,a1,a2,a3, af[kb][0][0],af[kb][0][1],af[kb][0][2],af[kb][0][3],
                         bf0[kb], bf1[kb]);
                mma_tf32(d0,d1,d2,d3, af[kb][1][0],af[kb][1][1],af[kb][1][2],af[kb][1][3],
                         bf0[kb], bf1[kb]);
            }
            *(float2*)(g_x2 + (size_t)(ob32+g)*PPOS      + p0 + pbase + 2*t4) = make_float2(a0,a1);
            *(float2*)(g_x2 + (size_t)(ob32+g+8)*PPOS    + p0 + pbase + 2*t4) = make_float2(a2,a3);
            *(float2*)(g_x2 + (size_t)(ob32+16+g)*PPOS   + p0 + pbase + 2*t4) = make_float2(d0,d1);
            *(float2*)(g_x2 + (size_t)(ob32+16+g+8)*PPOS + p0 + pbase + 2*t4) = make_float2(d2,d3);
            st_s[0] += a0 + a1; st_q[0] = fmaf(a0,a0,fmaf(a1,a1,st_q[0]));
            st_s[1] += a2 + a3; st_q[1] = fmaf(a2,a2,fmaf(a3,a3,st_q[1]));
            st_s[2] += d0 + d1; st_q[2] = fmaf(d0,d0,fmaf(d1,d1,st_q[2]));
            st_s[3] += d2 + d3; st_q[3] = fmaf(d2,d2,fmaf(d3,d3,st_q[3]));
        }
        tile = next;
    }
    // flush BN2 stat partials
#pragma unroll
    for (int d = 1; d < 4; d <<= 1)
#pragma unroll
        for (int i = 0; i < 4; ++i) {
            st_s[i] += __shfl_xor_sync(0xFFFFFFFFu, st_s[i], d);
            st_q[i] += __shfl_xor_sync(0xFFFFFFFFu, st_q[i], d);
        }
    if (t4 == 0) {
        int ch[4] = { ob32+g, ob32+g+8, ob32+16+g, ob32+16+g+8 };
#pragma unroll
        for (int i = 0; i < 4; ++i) {
            atomicAdd(&g_stats[ch[i]],      st_s[i]);
            atomicAdd(&g_stats[64 + ch[i]], st_q[i]);
        }
    }
}

// PERSISTENT layer3: warp = 32 outputs (2 m16) x 64 positions.
__global__ __launch_bounds__(256,2) void mlp3_kernel(const float* __restrict__ w2,
                                                     const float* __restrict__ b2,
                                                     const float* __restrict__ g1,
                                                     const float* __restrict__ beta1)
{
    extern __shared__ char smraw[];
    float* sab = (float*)smraw;                 // 128 (BN2 A/B)
    float* tx  = (float*)(smraw + 512);         // 64 rows x TXS floats
    __shared__ int s_next;
    const int tid  = threadIdx.x;
    const int lane = tid & 31, wid = tid >> 5;
    const int ob = (wid & 3) * 32;              // 32 outputs
    const int ph = (wid >> 2) * 64;             // position half
    const int g  = lane >> 2;
    const int t4 = lane & 3;

    if (tid < 64) {
        const float invP = 1.0f / (float)PPOS;
        float mean = g_stats[tid]    * invP;
        float var  = g_stats[64+tid] * invP - mean*mean;
        float A = g1[tid] * rsqrtf(var + 1e-5f);
        sab[tid]    = A;
        sab[64+tid] = fmaf(-mean, A, beta1[tid]);
    }

    unsigned af[8][2][4];
#pragma unroll
    for (int kb = 0; kb < 8; ++kb)
#pragma unroll
        for (int mb = 0; mb < 2; ++mb) {
            int r = ob + mb*16;
            af[kb][mb][0] = __float_as_uint(w2[(r+g)*64   + kb*8 + t4]);
            af[kb][mb][1] = __float_as_uint(w2[(r+g+8)*64 + kb*8 + t4]);
            af[kb][mb][2] = __float_as_uint(w2[(r+g)*64   + kb*8 + t4 + 4]);
            af[kb][mb][3] = __float_as_uint(w2[(r+g+8)*64 + kb*8 + t4 + 4]);
        }
    const float bias0l = b2[ob+g],    bias0h = b2[ob+g+8];
    const float bias1l = b2[ob+16+g], bias1h = b2[ob+16+g+8];
    float st_s[4] = {0,0,0,0}, st_q[4] = {0,0,0,0};

    int tile = blockIdx.x;
#pragma unroll
    for (int k = 0; k < 8; ++k) {
        int i = tid + k*256;
        int c = i >> 5, pp = (i & 31) * 4;
        cp_async16(tx + c*TXS + pp, g_x2 + (size_t)c*PPOS + tile*128 + pp);
    }
    cp_commit(); cp_wait0();
    __syncthreads();

    while (tile < PPOS/128) {
        if (tid == 0) s_next = NPERS + atomicAdd(&g_ctr[1], 1);
        for (int k = 0; k < 8; ++k) {
            int i = tid + k*256;
            int c = i >> 5, pp = (i & 31) * 4;
            float A = sab[c], Bv = sab[64+c];
            float4 v = *(float4*)(tx + c*TXS + pp);
            v.x = fmaxf(fmaf(v.x,A,Bv),0.f); v.y = fmaxf(fmaf(v.y,A,Bv),0.f);
            v.z = fmaxf(fmaf(v.z,A,Bv),0.f); v.w = fmaxf(fmaf(v.w,A,Bv),0.f);
            *(float4*)(tx + c*TXS + pp) = v;
        }
        __syncthreads();
        const int next = s_next;

#pragma unroll
        for (int grp2 = 0; grp2 < 2; ++grp2) {    // 2 groups of 32 positions
            float pmax[4] = {-3.4e38f,-3.4e38f,-3.4e38f,-3.4e38f};
            float pmin[4] = { 3.4e38f, 3.4e38f, 3.4e38f, 3.4e38f};
#pragma unroll
            for (int nbi = 0; nbi < 4; ++nbi) {
                const int pbase = ph + grp2*32 + nbi*8;
                unsigned bf0[8], bf1[8];
#pragma unroll
                for (int kb = 0; kb < 8; ++kb) {
                    bf0[kb] = __float_as_uint(tx[(kb*8 + t4)*TXS     + pbase + g]);
                    bf1[kb] = __float_as_uint(tx[(kb*8 + t4 + 4)*TXS + pbase + g]);
                }
                float a0 = bias0l, a1 = bias0l, a2 = bias0h, a3 = bias0h;
                float d0 = bias1l, d1 = bias1l, d2 = bias1h, d3 = bias1h;
#pragma unroll
                for (int kb = 0; kb < 8; ++kb) {
                    mma_tf32(a0,a1,a2,a3, af[kb][0][0],af[kb][0][1],af[kb][0][2],af[kb][0][3],
                             bf0[kb], bf1[kb]);
                    mma_tf32(d0,d1,d2,d3, af[kb][1][0],af[kb][1][1],af[kb][1][2],af[kb][1][3],
                             bf0[kb], bf1[kb]);
                }
                st_s[0] += a0 + a1; st_q[0] = fmaf(a0,a0,fmaf(a1,a1,st_q[0]));
                st_s[1] += a2 + a3; st_q[1] = fmaf(a2,a2,fmaf(a3,a3,st_q[1]));
                st_s[2] += d0 + d1; st_q[2] = fmaf(d0,d0,fmaf(d1,d1,st_q[2]));
                st_s[3] += d2 + d3; st_q[3] = fmaf(d2,d2,fmaf(d3,d3,st_q[3]));
                pmax[0] = fmaxf(pmax[0], fmaxf(a0,a1)); pmin[0] = fminf(pmin[0], fminf(a0,a1));
                pmax[1] = fmaxf(pmax[1], fmaxf(a2,a3)); pmin[1] = fminf(pmin[1], fminf(a2,a3));
                pmax[2] = fmaxf(pmax[2], fmaxf(d0,d1)); pmin[2] = fminf(pmin[2], fminf(d0,d1));
                pmax[3] = fmaxf(pmax[3], fmaxf(d2,d3)); pmin[3] = fminf(pmin[3], fminf(d2,d3));
            }
#pragma unroll
            for (int d = 1; d < 4; d <<= 1)
#pragma unroll
                for (int i = 0; i < 4; ++i) {
                    pmax[i] = fmaxf(pmax[i], __shfl_xor_sync(0xFFFFFFFFu, pmax[i], d));
                    pmin[i] = fminf(pmin[i], __shfl_xor_sync(0xFFFFFFFFu, pmin[i], d));
                }
            if (t4 == 0) {
                int gid = tile*4 + (ph >> 5) + grp2;   // ph/64*2 + grp2
                int ch[4] = { ob+g, ob+g+8, ob+16+g, ob+16+g+8 };
#pragma unroll
                for (int i = 0; i < 4; ++i)
                    g_pool[ch[i]*NGRP + gid] = make_float2(pmax[i], pmin[i]);
            }
        }
        __syncthreads();

        if (next < PPOS/128) {
#pragma unroll
            for (int k = 0; k < 8; ++k) {
                int i = tid + k*256;
                int c = i >> 5, pp = (i & 31) * 4;
                cp_async16(tx + c*TXS + pp, g_x2 + (size_t)c*PPOS + next*128 + pp);
            }
        }
        cp_commit(); cp_wait0();
        __syncthreads();
        tile = next;
    }
#pragma unroll
    for (int d = 1; d < 4; d <<= 1)
#pragma unroll
        for (int i = 0; i < 4; ++i) {
            st_s[i] += __shfl_xor_sync(0xFFFFFFFFu, st_s[i], d);
            st_q[i] += __shfl_xor_sync(0xFFFFFFFFu, st_q[i], d);
        }
    if (t4 == 0) {
        int ch[4] = { ob+g, ob+g+8, ob+16+g, ob+16+g+8 };
#pragma unroll
        for (int i = 0; i < 4; ++i) {
            atomicAdd(&g_stats[128 + ch[i]], st_s[i]);
            atomicAdd(&g_stats[256 + ch[i]], st_q[i]);
        }
    }
}

// Final: inline BN3 fold + affine+relu on pooled max/min. One CTA per (b,o).
__global__ __launch_bounds__(256) void final_kernel(float* __restrict__ out,
                                                    const float* __restrict__ g2,
                                                    const float* __restrict__ beta2)
{
    __shared__ float sA, sB;
    const int o = blockIdx.x & 127;
    const int b = blockIdx.x >> 7;
    if (threadIdx.x == 0) {
        const float invP = 1.0f / (float)PPOS;
        float mean = g_stats[128+o] * invP;
        float var  = g_stats[256+o] * invP - mean*mean;
        float A = g2[o] * rsqrtf(var + 1e-5f);
        sA = A; sB = fmaf(-mean, A, beta2[o]);
    }
    __syncthreads();
    float A = sA, Bv = sB;
    int s = threadIdx.x * 2;
    float2 p0 = g_pool[o*NGRP + b*SS + s];
    float2 p1 = g_pool[o*NGRP + b*SS + s + 1];
    float v0 = (A >= 0.0f) ? p0.x : p0.y;
    float v1 = (A >= 0.0f) ? p1.x : p1.y;
    float2 r;
    r.x = fmaxf(fmaf(v0, A, Bv), 0.0f);
    r.y = fmaxf(fmaf(v1, A, Bv), 0.0f);
    *(float2*)(out + ((b*128 + o) << 9) + s) = r;
}

// ---------------- launch ----------------
extern "C" void kernel_launch(void* const* d_in, const int* in_sizes, int n_in,
                              void* d_out, int out_size)
{
    const float* xyz = (const float*)d_in[0];
    const float* pts = (const float*)d_in[1];
    const float* w0  = (const float*)d_in[2];
    const float* b0  = (const float*)d_in[3];
    const float* gm0 = (const float*)d_in[4];
    const float* be0 = (const float*)d_in[5];
    const float* w1  = (const float*)d_in[6];
    const float* b1  = (const float*)d_in[7];
    const float* gm1 = (const float*)d_in[8];
    const float* be1 = (const float*)d_in[9];
    const float* w2  = (const float*)d_in[10];
    const float* b2  = (const float*)d_in[11];
    const float* gm2 = (const float*)d_in[12];
    const float* be2 = (const float*)d_in[13];
    float* out = (float*)d_out;

    cudaFuncSetAttribute(fps_kernel,     cudaFuncAttributeMaxDynamicSharedMemorySize, 73728);
    cudaFuncSetAttribute(fused12_kernel, cudaFuncAttributeMaxDynamicSharedMemorySize, 77312);
    cudaFuncSetAttribute(mlp3_kernel,    cudaFuncAttributeMaxDynamicSharedMemorySize, 35328);

    fps_kernel<<<BB, 512, 73728>>>(xyz, out);
    group_kernel<<<(BB*SS)/8, 256>>>(xyz, pts);
    fused12_kernel<<<NPERS, 256, 77312>>>(w0, b0, gm0, be0, w1, b1);
    mlp3_kernel<<<NPERS, 256, 35328>>>(w2, b2, gm1, be1);
    final_kernel<<<BB*128, 256>>>(out + BB*3*SS, gm2, be2);
}

// round 15
// speedup vs baseline: 1.1296x; 1.1296x over previous
#include <cuda_runtime.h>
#include <cuda_fp16.h>

#define BB 16
#define NN 4096
#define SS 512
#define NSAMP 32
#define PPOS (BB*SS*NSAMP)   // 262144 positions
#define NGRP (BB*SS)         // 8192 (b,s) groups
#define NPERS 296            // persistent grid (2 CTAs x 148 SMs)
#define TXS 136              // f32 mma tile row stride (floats)
#define TAS 264              // fused12 stage-A tile row stride (floats)
#define THB 272              // mlp3 fp16 staging row stride (bytes, 16B-aligned)

// ---------------- device scratch ----------------
__device__ float g_feat[6*PPOS];        // grouped features [c][p]
__device__ __half g_x2h[64*PPOS];       // layer2 raw conv out (fp16, 34MB)
__device__ float2 g_pool[128*NGRP];     // {max,min} of raw layer3 per group
__device__ float g_stats[384];          // [0..127] L2 sum/sumsq, [128..383] L3
__device__ float g_gram[27*32];         // 27 moments, line-padded
__device__ float4 g_new[NGRP];          // centroid x,y,z,|c|^2
__device__ int   g_ctr[2];              // work-steal counters

// ---------------- helpers ----------------
__device__ __forceinline__ unsigned long long fma2(unsigned long long a,
                                                   unsigned long long b,
                                                   unsigned long long c) {
    unsigned long long d;
    asm("fma.rn.f32x2 %0, %1, %2, %3;" : "=l"(d) : "l"(a), "l"(b), "l"(c));
    return d;
}
__device__ __forceinline__ unsigned long long add2(unsigned long long a,
                                                   unsigned long long b) {
    unsigned long long d;
    asm("add.rn.f32x2 %0, %1, %2;" : "=l"(d) : "l"(a), "l"(b));
    return d;
}
__device__ __forceinline__ unsigned long long mul2(unsigned long long a,
                                                   unsigned long long b) {
    unsigned long long d;
    asm("mul.rn.f32x2 %0, %1, %2;" : "=l"(d) : "l"(a), "l"(b));
    return d;
}
__device__ __forceinline__ unsigned long long pack2(float lo, float hi) {
    unsigned long long d;
    asm("mov.b64 %0, {%1, %2};" : "=l"(d) : "f"(lo), "f"(hi));
    return d;
}
__device__ __forceinline__ float2 unpack2(unsigned long long v) {
    float2 r;
    asm("mov.b64 {%0, %1}, %2;" : "=f"(r.x), "=f"(r.y) : "l"(v));
    return r;
}
__device__ __forceinline__ void cp_async16(void* smem_dst, const void* gmem_src) {
    unsigned s = (unsigned)__cvta_generic_to_shared(smem_dst);
    asm volatile("cp.async.cg.shared.global [%0], [%1], 16;" :: "r"(s), "l"(gmem_src) : "memory");
}
__device__ __forceinline__ void cp_commit() { asm volatile("cp.async.commit_group;" ::: "memory"); }
__device__ __forceinline__ void cp_wait0()  { asm volatile("cp.async.wait_group 0;"  ::: "memory"); }

__device__ __forceinline__ void mma_tf32(float& c0, float& c1, float& c2, float& c3,
                                         unsigned a0, unsigned a1, unsigned a2, unsigned a3,
                                         unsigned b0, unsigned b1) {
    asm("mma.sync.aligned.m16n8k8.row.col.f32.tf32.tf32.f32 "
        "{%0,%1,%2,%3}, {%4,%5,%6,%7}, {%8,%9}, {%0,%1,%2,%3};"
        : "+f"(c0), "+f"(c1), "+f"(c2), "+f"(c3)
        : "r"(a0), "r"(a1), "r"(a2), "r"(a3), "r"(b0), "r"(b1));
}

// FPS: 1 CTA/batch, 512 threads, 8 pts/thread packed as f32x2 pairs.
__global__ __launch_bounds__(512) void fps_kernel(const float* __restrict__ xyz,
                                                  float* __restrict__ out_newxyz)
{
    extern __shared__ float sh[];
    float4* pts4 = (float4*)sh;
    float4* cbuf = (float4*)(sh + 4*NN);
    __shared__ unsigned long long wkey[2][16];
    const int b = blockIdx.x, t = threadIdx.x;
    const int lane = t & 31, wid = t >> 5;
    const float* X = xyz + b*3*NN;

    if (b == 0) {
        if (t < 384) g_stats[t] = 0.0f;
        for (int i = t; i < 27*32; i += 512) g_gram[i] = 0.0f;
        if (t == 0) { g_ctr[0] = 0; g_ctr[1] = 0; }
    }

    float xv[8], yv[8], zv[8], dist[8];
#pragma unroll
    for (int k = 0; k < 8; ++k) {
        int n = t + k*512;
        xv[k] = X[n]; yv[k] = X[NN+n]; zv[k] = X[2*NN+n];
        pts4[n] = make_float4(-xv[k], -yv[k], -zv[k], 0.0f);
        dist[k] = 1e10f;
    }
    unsigned long long px2[4], py2[4], pz2[4];
#pragma unroll
    for (int j = 0; j < 4; ++j) {
        px2[j] = pack2(xv[2*j], xv[2*j+1]);
        py2[j] = pack2(yv[2*j], yv[2*j+1]);
        pz2[j] = pack2(zv[2*j], zv[2*j+1]);
    }
    __syncthreads();

    int far = 0;
    for (int s = 0; s < SS; ++s) {
        float4 cn = pts4[far];
        if (t == 0) cbuf[s] = cn;
        unsigned long long cx2 = pack2(cn.x, cn.x);
        unsigned long long cy2 = pack2(cn.y, cn.y);
        unsigned long long cz2 = pack2(cn.z, cn.z);
#pragma unroll
        for (int j = 0; j < 4; ++j) {
            unsigned long long dx2 = add2(px2[j], cx2);
            unsigned long long dy2 = add2(py2[j], cy2);
            unsigned long long dz2 = add2(pz2[j], cz2);
            unsigned long long d2 = mul2(dx2, dx2);
            d2 = fma2(dy2, dy2, d2);
            d2 = fma2(dz2, dz2, d2);
            float2 dd = unpack2(d2);
            dist[2*j]   = fminf(dist[2*j],   dd.x);
            dist[2*j+1] = fminf(dist[2*j+1], dd.y);
        }
        float v0 = dist[0]; int q0 = 0;
        if (dist[1] > v0) { v0 = dist[1]; q0 = 1; }
        float v1 = dist[2]; int q1 = 2;
        if (dist[3] > v1) { v1 = dist[3]; q1 = 3; }
        float v2 = dist[4]; int q2 = 4;
        if (dist[5] > v2) { v2 = dist[5]; q2 = 5; }
        float v3 = dist[6]; int q3 = 6;
        if (dist[7] > v3) { v3 = dist[7]; q3 = 7; }
        if (v1 > v0) { v0 = v1; q0 = q1; }
        if (v3 > v2) { v2 = v3; q2 = q3; }
        if (v2 > v0) { v0 = v2; q0 = q2; }
        int mi = t + q0*512;

        unsigned db = __float_as_uint(v0);
        unsigned wm = __reduce_max_sync(0xFFFFFFFFu, db);
        unsigned lo = __reduce_max_sync(0xFFFFFFFFu, (db == wm) ? ~(unsigned)mi : 0u);
        if (lane == 0) wkey[s & 1][wid] = ((unsigned long long)wm << 32) | lo;
        __syncthreads();
        unsigned long long k2 = wkey[s & 1][lane & 15];
        unsigned hi = (unsigned)(k2 >> 32), l2v = (unsigned)k2;
        unsigned m2 = __reduce_max_sync(0xFFFFFFFFu, hi);
        unsigned lw = __reduce_max_sync(0xFFFFFFFFu, (hi == m2) ? l2v : 0u);
        far = (int)(~lw);
    }
    __syncthreads();
    {
        float4 cn = cbuf[t];
        float cx = -cn.x, cy = -cn.y, cz = -cn.z;
        out_newxyz[(b*3+0)*SS + t] = cx;
        out_newxyz[(b*3+1)*SS + t] = cy;
        out_newxyz[(b*3+2)*SS + t] = cz;
        float sn = fmaf(cz,cz,fmaf(cy,cy,cx*cx));
        g_new[b*SS+t] = make_float4(cx,cy,cz,sn);
    }
}

// Ball query + gather + fused 27-moment accumulation. One warp per centroid.
__global__ __launch_bounds__(256) void group_kernel(const float* __restrict__ xyz,
                                                    const float* __restrict__ pts)
{
    __shared__ int sel[8][NSAMP];
    __shared__ float red[27];
    const int lane = threadIdx.x & 31, w = threadIdx.x >> 5;
    const int tid = threadIdx.x;
    if (tid < 27) red[tid] = 0.0f;
    __syncthreads();

    const int id = blockIdx.x*8 + w;
    const int b = id >> 9;
    const float4 c4 = g_new[id];
    const float* X = xyz + b*3*NN;
    const float* Q = pts + b*3*NN;
    const float R2 = (float)(0.4*0.4);

    int cnt = 0;
    for (int base = 0; base < NN && cnt < NSAMP; base += 32) {
        int n = base + lane;
        float x = X[n], y = X[NN+n], z = X[2*NN+n];
        float sx  = fmaf(z,z,fmaf(y,y,x*x));
        float dot = fmaf(z,c4.z,fmaf(y,c4.y,x*c4.x));
        float sq  = (c4.w + sx) - 2.0f*dot;
        bool pred = (sq <= R2);
        unsigned m = __ballot_sync(0xFFFFFFFFu, pred);
        if (pred) {
            int pos = cnt + __popc(m & ((1u << lane) - 1u));
            if (pos < NSAMP) sel[w][pos] = n;
        }
        cnt += __popc(m);
    }
    __syncwarp();
    int total = cnt < NSAMP ? cnt : NSAMP;
    int idx = sel[w][lane < total ? lane : 0];

    float f[6];
    f[0] = X[idx]      - c4.x;
    f[1] = X[NN+idx]   - c4.y;
    f[2] = X[2*NN+idx] - c4.z;
    f[3] = Q[idx];
    f[4] = Q[NN+idx];
    f[5] = Q[2*NN+idx];

    int p = id*NSAMP + lane;
#pragma unroll
    for (int c = 0; c < 6; ++c) g_feat[c*PPOS + p] = f[c];

    float v[27];
#pragma unroll
    for (int c = 0; c < 6; ++c) v[c] = f[c];
    {
        int k = 6;
#pragma unroll
        for (int i = 0; i < 6; ++i)
#pragma unroll
            for (int j = i; j < 6; ++j) { v[k] = f[i]*f[j]; ++k; }
    }
#pragma unroll
    for (int off = 16; off; off >>= 1)
#pragma unroll
        for (int i = 0; i < 27; ++i)
            v[i] += __shfl_down_sync(0xFFFFFFFFu, v[i], off);
    if (lane == 0)
#pragma unroll
        for (int i = 0; i < 27; ++i) atomicAdd(&red[i], v[i]);
    __syncthreads();
    if (tid < 27) atomicAdd(&g_gram[tid*32], red[tid]);
}

// PERSISTENT fused layer1+layer2 (R13 structure; x2 stored fp16).
__global__ __launch_bounds__(256,2) void fused12_kernel(const float* __restrict__ w0,
                                                        const float* __restrict__ b0,
                                                        const float* __restrict__ g0,
                                                        const float* __restrict__ beta0,
                                                        const float* __restrict__ w1,
                                                        const float* __restrict__ b1)
{
    extern __shared__ char smraw[];
    unsigned long long* w0d = (unsigned long long*)smraw;   // 384 ull (3072B)
    float* sab = (float*)(smraw + 3072);                    // 128 (BN1 A/B)
    float* tf  = (float*)(smraw + 3584);                    // 6 x 256 (6144B)
    float* tx  = (float*)(smraw + 9728);                    // 64 x TAS floats (67584B)
    __shared__ int s_next;
    const int tid  = threadIdx.x;
    const int lane = tid & 31, wid = tid >> 5;
    const int ob8  = wid * 8;
    const int ob16 = (wid & 3) * 16;
    const int ph   = (wid >> 2) * 128;
    const int g  = lane >> 2;
    const int t4 = lane & 3;

    if (tid < 64) {
        const int o = tid;
        float w[6];
#pragma unroll
        for (int c = 0; c < 6; ++c) w[c] = w0[o*6+c];
        float wS = 0.0f;
#pragma unroll
        for (int c = 0; c < 6; ++c) wS = fmaf(w[c], g_gram[c*32], wS);
        float quad = 0.0f; int idx = 6;
#pragma unroll
        for (int i = 0; i < 6; ++i)
#pragma unroll
            for (int j = i; j < 6; ++j) {
                float coef = (i == j) ? 1.0f : 2.0f;
                quad = fmaf(coef * w[i] * w[j], g_gram[idx*32], quad);
                ++idx;
            }
        float bo = b0[o];
        const float invP = 1.0f / (float)PPOS;
        float m   = fmaf(wS, invP, bo);
        float Ex2 = quad*invP + 2.0f*bo*wS*invP + bo*bo;
        float A = g0[o] * rsqrtf(Ex2 - m*m + 1e-5f);
        sab[o]    = A;
        sab[64+o] = fmaf(bo - m, A, beta0[o]);
    }
    for (int i = tid; i < 384; i += 256) { float v = w0[i]; w0d[i] = pack2(v,v); }

    unsigned af[8][4];
#pragma unroll
    for (int kb = 0; kb < 8; ++kb) {
        af[kb][0] = __float_as_uint(w1[(ob16+g)*64   + kb*8 + t4]);
        af[kb][1] = __float_as_uint(w1[(ob16+g+8)*64 + kb*8 + t4]);
        af[kb][2] = __float_as_uint(w1[(ob16+g)*64   + kb*8 + t4 + 4]);
        af[kb][3] = __float_as_uint(w1[(ob16+g+8)*64 + kb*8 + t4 + 4]);
    }
    const float bias_lo = b1[ob16+g], bias_hi = b1[ob16+g+8];
    float st_s_lo = 0.f, st_q_lo = 0.f, st_s_hi = 0.f, st_q_hi = 0.f;

    int tile = blockIdx.x;
    while (tile < PPOS/256) {
        const int p0 = tile * 256;
        if (tid == 0) s_next = NPERS + atomicAdd(&g_ctr[0], 1);
        __syncthreads();
        const int next = s_next;
        for (int i = tid; i < 384; i += 256) {
            int c = i >> 6, pp = (i & 63) * 4;
            *(float4*)(tf + c*256 + pp) = *(const float4*)(g_feat + c*PPOS + p0 + pp);
        }
        __syncthreads();

        // ---- stage A: 6 -> 64 (f32x2, BN1 affine + relu into padded tx) ----
        {
            unsigned long long a[8][4];
#pragma unroll
            for (int j = 0; j < 8; ++j)
#pragma unroll
                for (int q = 0; q < 4; ++q) a[j][q] = 0ull;
#pragma unroll
            for (int c = 0; c < 6; ++c) {
                ulonglong2 iv0 = *(const ulonglong2*)(tf + c*256 + lane*4);
                ulonglong2 iv1 = *(const ulonglong2*)(tf + c*256 + 128 + lane*4);
#pragma unroll
                for (int j = 0; j < 8; ++j) {
                    unsigned long long wv = w0d[(ob8+j)*6 + c];
                    a[j][0] = fma2(wv, iv0.x, a[j][0]);
                    a[j][1] = fma2(wv, iv0.y, a[j][1]);
                    a[j][2] = fma2(wv, iv1.x, a[j][2]);
                    a[j][3] = fma2(wv, iv1.y, a[j][3]);
                }
            }
#pragma unroll
            for (int j = 0; j < 8; ++j) {
                float A = sab[ob8+j], Bv = sab[64+ob8+j];
#pragma unroll
                for (int s2 = 0; s2 < 2; ++s2) {
                    float2 u = unpack2(a[j][s2*2+0]);
                    float2 v = unpack2(a[j][s2*2+1]);
                    float4 o4;
                    o4.x = fmaxf(fmaf(u.x,A,Bv),0.f);
                    o4.y = fmaxf(fmaf(u.y,A,Bv),0.f);
                    o4.z = fmaxf(fmaf(v.x,A,Bv),0.f);
                    o4.w = fmaxf(fmaf(v.y,A,Bv),0.f);
                    *(float4*)(tx + (ob8+j)*TAS + s2*128 + lane*4) = o4;
                }
            }
        }
        __syncthreads();

        // ---- stage B: 64 -> 64 via tf32 mma; fp16 x2 out + register stats ----
#pragma unroll
        for (int nb = 0; nb < 16; ++nb) {
            const int pbase = ph + nb*8;
            unsigned bf0[8], bf1[8];
#pragma unroll
            for (int kb = 0; kb < 8; ++kb) {
                bf0[kb] = __float_as_uint(tx[(kb*8 + t4)*TAS     + pbase + g]);
                bf1[kb] = __float_as_uint(tx[(kb*8 + t4 + 4)*TAS + pbase + g]);
            }
            float e0 = bias_lo, e1 = bias_lo, e2 = bias_hi, e3 = bias_hi;
            float o0 = 0.f, o1 = 0.f, o2 = 0.f, o3 = 0.f;
#pragma unroll
            for (int kb = 0; kb < 8; kb += 2) {
                mma_tf32(e0,e1,e2,e3, af[kb][0],af[kb][1],af[kb][2],af[kb][3],
                         bf0[kb], bf1[kb]);
                mma_tf32(o0,o1,o2,o3, af[kb+1][0],af[kb+1][1],af[kb+1][2],af[kb+1][3],
                         bf0[kb+1], bf1[kb+1]);
            }
            float c0 = e0+o0, c1 = e1+o1, c2 = e2+o2, c3 = e3+o3;
            *(__half2*)(g_x2h + (size_t)(ob16+g)*PPOS   + p0 + pbase + 2*t4) = __floats2half2_rn(c0,c1);
            *(__half2*)(g_x2h + (size_t)(ob16+g+8)*PPOS + p0 + pbase + 2*t4) = __floats2half2_rn(c2,c3);
            st_s_lo += c0 + c1; st_q_lo = fmaf(c0,c0,fmaf(c1,c1,st_q_lo));
            st_s_hi += c2 + c3; st_q_hi = fmaf(c2,c2,fmaf(c3,c3,st_q_hi));
        }
        tile = next;
    }
#pragma unroll
    for (int d = 1; d < 4; d <<= 1) {
        st_s_lo += __shfl_xor_sync(0xFFFFFFFFu, st_s_lo, d);
        st_q_lo += __shfl_xor_sync(0xFFFFFFFFu, st_q_lo, d);
        st_s_hi += __shfl_xor_sync(0xFFFFFFFFu, st_s_hi, d);
        st_q_hi += __shfl_xor_sync(0xFFFFFFFFu, st_q_hi, d);
    }
    if (t4 == 0) {
        atomicAdd(&g_stats[ob16+g],        st_s_lo);
        atomicAdd(&g_stats[64 + ob16+g],   st_q_lo);
        atomicAdd(&g_stats[ob16+g+8],      st_s_hi);
        atomicAdd(&g_stats[64 + ob16+g+8], st_q_hi);
    }
}

// PERSISTENT layer3 (R14 warp layout): warp = 32 outputs x 64 positions.
// fp16 x2 staged -> BN2+relu converts into f32 mma tile; full fetch/mma overlap.
__global__ __launch_bounds__(256,2) void mlp3_kernel(const float* __restrict__ w2,
                                                     const float* __restrict__ b2,
                                                     const float* __restrict__ g1,
                                                     const float* __restrict__ beta1)
{
    extern __shared__ char smraw[];
    float* sab  = (float*)smraw;                  // 128 floats (512B)
    char*  txh  = smraw + 512;                    // 64 rows x THB bytes fp16 stage
    float* txf  = (float*)(smraw + 512 + 64*THB); // 64 x TXS floats (mma tile)
    __shared__ int s_next;
    const int tid  = threadIdx.x;
    const int lane = tid & 31, wid = tid >> 5;
    const int ob = (wid & 3) * 32;
    const int ph = (wid >> 2) * 64;
    const int g  = lane >> 2;
    const int t4 = lane & 3;

    if (tid < 64) {
        const float invP = 1.0f / (float)PPOS;
        float mean = g_stats[tid]    * invP;
        float var  = g_stats[64+tid] * invP - mean*mean;
        float A = g1[tid] * rsqrtf(var + 1e-5f);
        sab[tid]    = A;
        sab[64+tid] = fmaf(-mean, A, beta1[tid]);
    }

    unsigned af[8][2][4];
#pragma unroll
    for (int kb = 0; kb < 8; ++kb)
#pragma unroll
        for (int mb = 0; mb < 2; ++mb) {
            int r = ob + mb*16;
            af[kb][mb][0] = __float_as_uint(w2[(r+g)*64   + kb*8 + t4]);
            af[kb][mb][1] = __float_as_uint(w2[(r+g+8)*64 + kb*8 + t4]);
            af[kb][mb][2] = __float_as_uint(w2[(r+g)*64   + kb*8 + t4 + 4]);
            af[kb][mb][3] = __float_as_uint(w2[(r+g+8)*64 + kb*8 + t4 + 4]);
        }
    const float bias0l = b2[ob+g],    bias0h = b2[ob+g+8];
    const float bias1l = b2[ob+16+g], bias1h = b2[ob+16+g+8];
    float st_s[4] = {0,0,0,0}, st_q[4] = {0,0,0,0};

    int tile = blockIdx.x;
#pragma unroll
    for (int k = 0; k < 4; ++k) {          // 1024 16B chunks (64 rows x 16)
        int i = tid + k*256;
        int c = i >> 4, ch = i & 15;
        cp_async16(txh + c*THB + ch*16, g_x2h + (size_t)c*PPOS + tile*128 + ch*8);
    }
    cp_commit(); cp_wait0();
    __syncthreads();

    while (tile < PPOS/128) {
        if (tid == 0) s_next = NPERS + atomicAdd(&g_ctr[1], 1);
        // BN2 affine + relu: fp16 stage -> f32 mma tile
        for (int k = 0; k < 16; ++k) {     // 4096 half2 elements
            int i = tid + k*256;
            int c = i >> 6, j = i & 63;
            float A = sab[c], Bv = sab[64+c];
            __half2 hv = *(__half2*)(txh + c*THB + j*4);
            float2 f = __half22float2(hv);
            txf[c*TXS + 2*j]     = fmaxf(fmaf(f.x,A,Bv),0.f);
            txf[c*TXS + 2*j + 1] = fmaxf(fmaf(f.y,A,Bv),0.f);
        }
        __syncthreads();                   // txf ready; txh consumed; s_next published
        const int next = s_next;

        if (next < PPOS/128) {             // overlap next fetch with ENTIRE mma
#pragma unroll
            for (int k = 0; k < 4; ++k) {
                int i = tid + k*256;
                int c = i >> 4, ch = i & 15;
                cp_async16(txh + c*THB + ch*16, g_x2h + (size_t)c*PPOS + next*128 + ch*8);
            }
        }
        cp_commit();

#pragma unroll
        for (int grp2 = 0; grp2 < 2; ++grp2) {
            float pmax[4] = {-3.4e38f,-3.4e38f,-3.4e38f,-3.4e38f};
            float pmin[4] = { 3.4e38f, 3.4e38f, 3.4e38f, 3.4e38f};
#pragma unroll
            for (int nbi = 0; nbi < 4; ++nbi) {
                const int pbase = ph + grp2*32 + nbi*8;
                unsigned bf0[8], bf1[8];
#pragma unroll
                for (int kb = 0; kb < 8; ++kb) {
                    bf0[kb] = __float_as_uint(txf[(kb*8 + t4)*TXS     + pbase + g]);
                    bf1[kb] = __float_as_uint(txf[(kb*8 + t4 + 4)*TXS + pbase + g]);
                }
                float a0 = bias0l, a1 = bias0l, a2 = bias0h, a3 = bias0h;
                float d0 = bias1l, d1 = bias1l, d2 = bias1h, d3 = bias1h;
#pragma unroll
                for (int kb = 0; kb < 8; ++kb) {
                    mma_tf32(a0,a1,a2,a3, af[kb][0][0],af[kb][0][1],af[kb][0][2],af[kb][0][3],
                             bf0[kb], bf1[kb]);
                    mma_tf32(d0,d1,d2,d3, af[kb][1][0],af[kb][1][1],af[kb][1][2],af[kb][1][3],
                             bf0[kb], bf1[kb]);
                }
                st_s[0] += a0 + a1; st_q[0] = fmaf(a0,a0,fmaf(a1,a1,st_q[0]));
                st_s[1] += a2 + a3; st_q[1] = fmaf(a2,a2,fmaf(a3,a3,st_q[1]));
                st_s[2] += d0 + d1; st_q[2] = fmaf(d0,d0,fmaf(d1,d1,st_q[2]));
                st_s[3] += d2 + d3; st_q[3] = fmaf(d2,d2,fmaf(d3,d3,st_q[3]));
                pmax[0] = fmaxf(pmax[0], fmaxf(a0,a1)); pmin[0] = fminf(pmin[0], fminf(a0,a1));
                pmax[1] = fmaxf(pmax[1], fmaxf(a2,a3)); pmin[1] = fminf(pmin[1], fminf(a2,a3));
                pmax[2] = fmaxf(pmax[2], fmaxf(d0,d1)); pmin[2] = fminf(pmin[2], fminf(d0,d1));
                pmax[3] = fmaxf(pmax[3], fmaxf(d2,d3)); pmin[3] = fminf(pmin[3], fminf(d2,d3));
            }
#pragma unroll
            for (int d = 1; d < 4; d <<= 1)
#pragma unroll
                for (int i = 0; i < 4; ++i) {
                    pmax[i] = fmaxf(pmax[i], __shfl_xor_sync(0xFFFFFFFFu, pmax[i], d));
                    pmin[i] = fminf(pmin[i], __shfl_xor_sync(0xFFFFFFFFu, pmin[i], d));
                }
            if (t4 == 0) {
                int gid = tile*4 + (ph >> 5) + grp2;
                int ch[4] = { ob+g, ob+g+8, ob+16+g, ob+16+g+8 };
#pragma unroll
                for (int i = 0; i < 4; ++i)
                    g_pool[ch[i]*NGRP + gid] = make_float2(pmax[i], pmin[i]);
            }
        }
        cp_wait0();
        __syncthreads();                   // txh full for next iter; txf free
        tile = next;
    }
#pragma unroll
    for (int d = 1; d < 4; d <<= 1)
#pragma unroll
        for (int i = 0; i < 4; ++i) {
            st_s[i] += __shfl_xor_sync(0xFFFFFFFFu, st_s[i], d);
            st_q[i] += __shfl_xor_sync(0xFFFFFFFFu, st_q[i], d);
        }
    if (t4 == 0) {
        int ch[4] = { ob+g, ob+g+8, ob+16+g, ob+16+g+8 };
#pragma unroll
        for (int i = 0; i < 4; ++i) {
            atomicAdd(&g_stats[128 + ch[i]], st_s[i]);
            atomicAdd(&g_stats[256 + ch[i]], st_q[i]);
        }
    }
}

// Final: inline BN3 fold + affine+relu on pooled max/min. One CTA per (b,o).
__global__ __launch_bounds__(256) void final_kernel(float* __restrict__ out,
                                                    const float* __restrict__ g2,
                                                    const float* __restrict__ beta2)
{
    __shared__ float sA, sB;
    const int o = blockIdx.x & 127;
    const int b = blockIdx.x >> 7;
    if (threadIdx.x == 0) {
        const float invP = 1.0f / (float)PPOS;
        float mean = g_stats[128+o] * invP;
        float var  = g_stats[256+o] * invP - mean*mean;
        float A = g2[o] * rsqrtf(var + 1e-5f);
        sA = A; sB = fmaf(-mean, A, beta2[o]);
    }
    __syncthreads();
    float A = sA, Bv = sB;
    int s = threadIdx.x * 2;
    float2 p0 = g_pool[o*NGRP + b*SS + s];
    float2 p1 = g_pool[o*NGRP + b*SS + s + 1];
    float v0 = (A >= 0.0f) ? p0.x : p0.y;
    float v1 = (A >= 0.0f) ? p1.x : p1.y;
    float2 r;
    r.x = fmaxf(fmaf(v0, A, Bv), 0.0f);
    r.y = fmaxf(fmaf(v1, A, Bv), 0.0f);
    *(float2*)(out + ((b*128 + o) << 9) + s) = r;
}

// ---------------- launch ----------------
extern "C" void kernel_launch(void* const* d_in, const int* in_sizes, int n_in,
                              void* d_out, int out_size)
{
    const float* xyz = (const float*)d_in[0];
    const float* pts = (const float*)d_in[1];
    const float* w0  = (const float*)d_in[2];
    const float* b0  = (const float*)d_in[3];
    const float* gm0 = (const float*)d_in[4];
    const float* be0 = (const float*)d_in[5];
    const float* w1  = (const float*)d_in[6];
    const float* b1  = (const float*)d_in[7];
    const float* gm1 = (const float*)d_in[8];
    const float* be1 = (const float*)d_in[9];
    const float* w2  = (const float*)d_in[10];
    const float* b2  = (const float*)d_in[11];
    const float* gm2 = (const float*)d_in[12];
    const float* be2 = (const float*)d_in[13];
    float* out = (float*)d_out;

    const int mlp3_smem = 512 + 64*THB + TXS*64*4;   // 512 + 17408 + 34816 = 52736

    cudaFuncSetAttribute(fps_kernel,     cudaFuncAttributeMaxDynamicSharedMemorySize, 73728);
    cudaFuncSetAttribute(fused12_kernel, cudaFuncAttributeMaxDynamicSharedMemorySize, 77312);
    cudaFuncSetAttribute(mlp3_kernel,    cudaFuncAttributeMaxDynamicSharedMemorySize, mlp3_smem);

    fps_kernel<<<BB, 512, 73728>>>(xyz, out);
    group_kernel<<<(BB*SS)/8, 256>>>(xyz, pts);
    fused12_kernel<<<NPERS, 256, 77312>>>(w0, b0, gm0, be0, w1, b1);
    mlp3_kernel<<<NPERS, 256, mlp3_smem>>>(w2, b2, gm1, be1);
    final_kernel<<<BB*128, 256>>>(out + BB*3*SS, gm2, be2);
}

// round 17
// speedup vs baseline: 1.1388x; 1.0081x over previous
#include <cuda_runtime.h>
#include <cuda_fp16.h>

#define BB 16
#define NN 4096
#define SS 512
#define NSAMP 32
#define PPOS (BB*SS*NSAMP)   // 262144 positions
#define NGRP (BB*SS)         // 8192 (b,s) groups
#define NPERS 296            // persistent grid (2 CTAs x 148 SMs)
#define TXS 136              // f32 mma tile row stride (floats)
#define TAS 264              // fused12 stage-A tile row stride (floats)
#define THB 272              // mlp3 fp16 staging row stride (bytes)

// ---------------- device scratch ----------------
__device__ float g_feat[6*PPOS];        // grouped features [c][p]
__device__ __half g_x2h[64*PPOS];       // layer2 raw conv out (fp16, 34MB)
__device__ float2 g_pool[128*NGRP];     // {max,min} of raw layer3 per group
__device__ float g_stats[384];          // [0..127] L2 sum/sumsq, [128..383] L3
__device__ float g_gram[27*32];         // 27 moments, line-padded
__device__ float4 g_new[NGRP];          // centroid x,y,z,|c|^2
__device__ int   g_ctr[2];              // work-steal counters

// ---------------- helpers ----------------
__device__ __forceinline__ unsigned long long fma2(unsigned long long a,
                                                   unsigned long long b,
                                                   unsigned long long c) {
    unsigned long long d;
    asm("fma.rn.f32x2 %0, %1, %2, %3;" : "=l"(d) : "l"(a), "l"(b), "l"(c));
    return d;
}
__device__ __forceinline__ unsigned long long add2(unsigned long long a,
                                                   unsigned long long b) {
    unsigned long long d;
    asm("add.rn.f32x2 %0, %1, %2;" : "=l"(d) : "l"(a), "l"(b));
    return d;
}
__device__ __forceinline__ unsigned long long mul2(unsigned long long a,
                                                   unsigned long long b) {
    unsigned long long d;
    asm("mul.rn.f32x2 %0, %1, %2;" : "=l"(d) : "l"(a), "l"(b));
    return d;
}
__device__ __forceinline__ unsigned long long pack2(float lo, float hi) {
    unsigned long long d;
    asm("mov.b64 %0, {%1, %2};" : "=l"(d) : "f"(lo), "f"(hi));
    return d;
}
__device__ __forceinline__ float2 unpack2(unsigned long long v) {
    float2 r;
    asm("mov.b64 {%0, %1}, %2;" : "=f"(r.x), "=f"(r.y) : "l"(v));
    return r;
}
__device__ __forceinline__ void cp_async16(void* smem_dst, const void* gmem_src) {
    unsigned s = (unsigned)__cvta_generic_to_shared(smem_dst);
    asm volatile("cp.async.cg.shared.global [%0], [%1], 16;" :: "r"(s), "l"(gmem_src) : "memory");
}
__device__ __forceinline__ void cp_commit() { asm volatile("cp.async.commit_group;" ::: "memory"); }
__device__ __forceinline__ void cp_wait0()  { asm volatile("cp.async.wait_group 0;"  ::: "memory"); }

__device__ __forceinline__ void mma_tf32(float& c0, float& c1, float& c2, float& c3,
                                         unsigned a0, unsigned a1, unsigned a2, unsigned a3,
                                         unsigned b0, unsigned b1) {
    asm("mma.sync.aligned.m16n8k8.row.col.f32.tf32.tf32.f32 "
        "{%0,%1,%2,%3}, {%4,%5,%6,%7}, {%8,%9}, {%0,%1,%2,%3};"
        : "+f"(c0), "+f"(c1), "+f"(c2), "+f"(c3)
        : "r"(a0), "r"(a1), "r"(a2), "r"(a3), "r"(b0), "r"(b1));
}

// FPS: 1 CTA/batch, 512 threads, 8 pts/thread packed as f32x2 pairs (R15-verified).
__global__ __launch_bounds__(512) void fps_kernel(const float* __restrict__ xyz,
                                                  float* __restrict__ out_newxyz)
{
    extern __shared__ float sh[];
    float4* pts4 = (float4*)sh;
    float4* cbuf = (float4*)(sh + 4*NN);
    __shared__ unsigned long long wkey[2][16];
    const int b = blockIdx.x, t = threadIdx.x;
    const int lane = t & 31, wid = t >> 5;
    const float* X = xyz + b*3*NN;

    if (b == 0) {
        if (t < 384) g_stats[t] = 0.0f;
        for (int i = t; i < 27*32; i += 512) g_gram[i] = 0.0f;
        if (t == 0) { g_ctr[0] = 0; g_ctr[1] = 0; }
    }

    float xv[8], yv[8], zv[8], dist[8];
#pragma unroll
    for (int k = 0; k < 8; ++k) {
        int n = t + k*512;
        xv[k] = X[n]; yv[k] = X[NN+n]; zv[k] = X[2*NN+n];
        pts4[n] = make_float4(-xv[k], -yv[k], -zv[k], 0.0f);
        dist[k] = 1e10f;
    }
    unsigned long long px2[4], py2[4], pz2[4];
#pragma unroll
    for (int j = 0; j < 4; ++j) {
        px2[j] = pack2(xv[2*j], xv[2*j+1]);
        py2[j] = pack2(yv[2*j], yv[2*j+1]);
        pz2[j] = pack2(zv[2*j], zv[2*j+1]);
    }
    __syncthreads();

    int far = 0;
    for (int s = 0; s < SS; ++s) {
        float4 cn = pts4[far];
        if (t == 0) cbuf[s] = cn;
        unsigned long long cx2 = pack2(cn.x, cn.x);
        unsigned long long cy2 = pack2(cn.y, cn.y);
        unsigned long long cz2 = pack2(cn.z, cn.z);
#pragma unroll
        for (int j = 0; j < 4; ++j) {
            unsigned long long dx2 = add2(px2[j], cx2);
            unsigned long long dy2 = add2(py2[j], cy2);
            unsigned long long dz2 = add2(pz2[j], cz2);
            unsigned long long d2 = mul2(dx2, dx2);
            d2 = fma2(dy2, dy2, d2);
            d2 = fma2(dz2, dz2, d2);
            float2 dd = unpack2(d2);
            dist[2*j]   = fminf(dist[2*j],   dd.x);
            dist[2*j+1] = fminf(dist[2*j+1], dd.y);
        }
        float v0 = dist[0]; int q0 = 0;
        if (dist[1] > v0) { v0 = dist[1]; q0 = 1; }
        float v1 = dist[2]; int q1 = 2;
        if (dist[3] > v1) { v1 = dist[3]; q1 = 3; }
        float v2 = dist[4]; int q2 = 4;
        if (dist[5] > v2) { v2 = dist[5]; q2 = 5; }
        float v3 = dist[6]; int q3 = 6;
        if (dist[7] > v3) { v3 = dist[7]; q3 = 7; }
        if (v1 > v0) { v0 = v1; q0 = q1; }
        if (v3 > v2) { v2 = v3; q2 = q3; }
        if (v2 > v0) { v0 = v2; q0 = q2; }
        int mi = t + q0*512;

        unsigned db = __float_as_uint(v0);
        unsigned wm = __reduce_max_sync(0xFFFFFFFFu, db);
        unsigned lo = __reduce_max_sync(0xFFFFFFFFu, (db == wm) ? ~(unsigned)mi : 0u);
        if (lane == 0) wkey[s & 1][wid] = ((unsigned long long)wm << 32) | lo;
        __syncthreads();
        unsigned long long k2 = wkey[s & 1][lane & 15];
        unsigned hi = (unsigned)(k2 >> 32), l2v = (unsigned)k2;
        unsigned m2 = __reduce_max_sync(0xFFFFFFFFu, hi);
        unsigned lw = __reduce_max_sync(0xFFFFFFFFu, (hi == m2) ? l2v : 0u);
        far = (int)(~lw);
    }
    __syncthreads();
    {
        float4 cn = cbuf[t];
        float cx = -cn.x, cy = -cn.y, cz = -cn.z;
        out_newxyz[(b*3+0)*SS + t] = cx;
        out_newxyz[(b*3+1)*SS + t] = cy;
        out_newxyz[(b*3+2)*SS + t] = cz;
        float sn = fmaf(cz,cz,fmaf(cy,cy,cx*cx));
        g_new[b*SS+t] = make_float4(cx,cy,cz,sn);
    }
}

// Ball query + gather + fused 27-moment accumulation. One warp per centroid.
__global__ __launch_bounds__(256) void group_kernel(const float* __restrict__ xyz,
                                                    const float* __restrict__ pts)
{
    __shared__ int sel[8][NSAMP];
    __shared__ float red[27];
    const int lane = threadIdx.x & 31, w = threadIdx.x >> 5;
    const int tid = threadIdx.x;
    if (tid < 27) red[tid] = 0.0f;
    __syncthreads();

    const int id = blockIdx.x*8 + w;
    const int b = id >> 9;
    const float4 c4 = g_new[id];
    const float* X = xyz + b*3*NN;
    const float* Q = pts + b*3*NN;
    const float R2 = (float)(0.4*0.4);

    int cnt = 0;
    for (int base = 0; base < NN && cnt < NSAMP; base += 32) {
        int n = base + lane;
        float x = X[n], y = X[NN+n], z = X[2*NN+n];
        float sx  = fmaf(z,z,fmaf(y,y,x*x));
        float dot = fmaf(z,c4.z,fmaf(y,c4.y,x*c4.x));
        float sq  = (c4.w + sx) - 2.0f*dot;
        bool pred = (sq <= R2);
        unsigned m = __ballot_sync(0xFFFFFFFFu, pred);
        if (pred) {
            int pos = cnt + __popc(m & ((1u << lane) - 1u));
            if (pos < NSAMP) sel[w][pos] = n;
        }
        cnt += __popc(m);
    }
    __syncwarp();
    int total = cnt < NSAMP ? cnt : NSAMP;
    int idx = sel[w][lane < total ? lane : 0];

    float f[6];
    f[0] = X[idx]      - c4.x;
    f[1] = X[NN+idx]   - c4.y;
    f[2] = X[2*NN+idx] - c4.z;
    f[3] = Q[idx];
    f[4] = Q[NN+idx];
    f[5] = Q[2*NN+idx];

    int p = id*NSAMP + lane;
#pragma unroll
    for (int c = 0; c < 6; ++c) g_feat[c*PPOS + p] = f[c];

    float v[27];
#pragma unroll
    for (int c = 0; c < 6; ++c) v[c] = f[c];
    {
        int k = 6;
#pragma unroll
        for (int i = 0; i < 6; ++i)
#pragma unroll
            for (int j = i; j < 6; ++j) { v[k] = f[i]*f[j]; ++k; }
    }
#pragma unroll
    for (int off = 16; off; off >>= 1)
#pragma unroll
        for (int i = 0; i < 27; ++i)
            v[i] += __shfl_down_sync(0xFFFFFFFFu, v[i], off);
    if (lane == 0)
#pragma unroll
        for (int i = 0; i < 27; ++i) atomicAdd(&red[i], v[i]);
    __syncthreads();
    if (tid < 27) atomicAdd(&g_gram[tid*32], red[tid]);
}

// PERSISTENT fused layer1+layer2; double-buffered g_feat prefetch; fp16 x2 out.
__global__ __launch_bounds__(256,2) void fused12_kernel(const float* __restrict__ w0,
                                                        const float* __restrict__ b0,
                                                        const float* __restrict__ g0,
                                                        const float* __restrict__ beta0,
                                                        const float* __restrict__ w1,
                                                        const float* __restrict__ b1)
{
    extern __shared__ char smraw[];
    unsigned long long* w0d = (unsigned long long*)smraw;   // 384 ull (3072B)
    float* sab = (float*)(smraw + 3072);                    // 128 (BN1 A/B)
    float* tf  = (float*)(smraw + 3584);                    // 2 x 6 x 256 (12288B)
    float* tx  = (float*)(smraw + 15872);                   // 64 x TAS floats (67584B)
    __shared__ int s_next;
    const int tid  = threadIdx.x;
    const int lane = tid & 31, wid = tid >> 5;
    const int ob8  = wid * 8;
    const int ob16 = (wid & 3) * 16;
    const int ph   = (wid >> 2) * 128;
    const int g  = lane >> 2;
    const int t4 = lane & 3;

    if (tid < 64) {
        const int o = tid;
        float w[6];
#pragma unroll
        for (int c = 0; c < 6; ++c) w[c] = w0[o*6+c];
        float wS = 0.0f;
#pragma unroll
        for (int c = 0; c < 6; ++c) wS = fmaf(w[c], g_gram[c*32], wS);
        float quad = 0.0f; int idx = 6;
#pragma unroll
        for (int i = 0; i < 6; ++i)
#pragma unroll
            for (int j = i; j < 6; ++j) {
                float coef = (i == j) ? 1.0f : 2.0f;
                quad = fmaf(coef * w[i] * w[j], g_gram[idx*32], quad);
                ++idx;
            }
        float bo = b0[o];
        const float invP = 1.0f / (float)PPOS;
        float m   = fmaf(wS, invP, bo);
        float Ex2 = quad*invP + 2.0f*bo*wS*invP + bo*bo;
        float A = g0[o] * rsqrtf(Ex2 - m*m + 1e-5f);
        sab[o]    = A;
        sab[64+o] = fmaf(bo - m, A, beta0[o]);
    }
    for (int i = tid; i < 384; i += 256) { float v = w0[i]; w0d[i] = pack2(v,v); }

    unsigned af[8][4];
#pragma unroll
    for (int kb = 0; kb < 8; ++kb) {
        af[kb][0] = __float_as_uint(w1[(ob16+g)*64   + kb*8 + t4]);
        af[kb][1] = __float_as_uint(w1[(ob16+g+8)*64 + kb*8 + t4]);
        af[kb][2] = __float_as_uint(w1[(ob16+g)*64   + kb*8 + t4 + 4]);
        af[kb][3] = __float_as_uint(w1[(ob16+g+8)*64 + kb*8 + t4 + 4]);
    }
    const float bias_lo = b1[ob16+g], bias_hi = b1[ob16+g+8];
    float st_s_lo = 0.f, st_q_lo = 0.f, st_s_hi = 0.f, st_q_hi = 0.f;

    int tile = blockIdx.x;
    int buf = 0;
    // prefetch first tile's feature slab (384 float4)
#pragma unroll
    for (int k = 0; k < 2; ++k) {
        int i = tid + k*256;
        if (i < 384) {
            int c = i >> 6, pp = (i & 63) * 4;
            cp_async16(tf + c*256 + pp, g_feat + (size_t)c*PPOS + tile*256 + pp);
        }
    }
    cp_commit();

    while (tile < PPOS/256) {
        const int p0 = tile * 256;
        if (tid == 0) s_next = NPERS + atomicAdd(&g_ctr[0], 1);
        cp_wait0();
        __syncthreads();          // tf[buf] ready; prev stage-B done with tx; s_next visible
        const int next = s_next;
        const float* tfb = tf + buf*1536;
        if (next < PPOS/256) {    // prefetch next tile into other buffer (overlaps A+B)
#pragma unroll
            for (int k = 0; k < 2; ++k) {
                int i = tid + k*256;
                if (i < 384) {
                    int c = i >> 6, pp = (i & 63) * 4;
                    cp_async16(tf + (buf^1)*1536 + c*256 + pp,
                               g_feat + (size_t)c*PPOS + next*256 + pp);
                }
            }
        }
        cp_commit();

        // ---- stage A: 6 -> 64 (f32x2, BN1 affine + relu into padded tx) ----
        {
            unsigned long long a[8][4];
#pragma unroll
            for (int j = 0; j < 8; ++j)
#pragma unroll
                for (int q = 0; q < 4; ++q) a[j][q] = 0ull;
#pragma unroll
            for (int c = 0; c < 6; ++c) {
                ulonglong2 iv0 = *(const ulonglong2*)(tfb + c*256 + lane*4);
                ulonglong2 iv1 = *(const ulonglong2*)(tfb + c*256 + 128 + lane*4);
#pragma unroll
                for (int j = 0; j < 8; ++j) {
                    unsigned long long wv = w0d[(ob8+j)*6 + c];
                    a[j][0] = fma2(wv, iv0.x, a[j][0]);
                    a[j][1] = fma2(wv, iv0.y, a[j][1]);
                    a[j][2] = fma2(wv, iv1.x, a[j][2]);
                    a[j][3] = fma2(wv, iv1.y, a[j][3]);
                }
            }
#pragma unroll
            for (int j = 0; j < 8; ++j) {
                float A = sab[ob8+j], Bv = sab[64+ob8+j];
#pragma unroll
                for (int s2 = 0; s2 < 2; ++s2) {
                    float2 u = unpack2(a[j][s2*2+0]);
                    float2 v = unpack2(a[j][s2*2+1]);
                    float4 o4;
                    o4.x = fmaxf(fmaf(u.x,A,Bv),0.f);
                    o4.y = fmaxf(fmaf(u.y,A,Bv),0.f);
                    o4.z = fmaxf(fmaf(v.x,A,Bv),0.f);
                    o4.w = fmaxf(fmaf(v.y,A,Bv),0.f);
                    *(float4*)(tx + (ob8+j)*TAS + s2*128 + lane*4) = o4;
                }
            }
        }
        __syncthreads();

        // ---- stage B: 64 -> 64 via tf32 mma; fp16 x2 out + register stats ----
#pragma unroll
        for (int nb = 0; nb < 16; ++nb) {
            const int pbase = ph + nb*8;
            unsigned bf0[8], bf1[8];
#pragma unroll
            for (int kb = 0; kb < 8; ++kb) {
                bf0[kb] = __float_as_uint(tx[(kb*8 + t4)*TAS     + pbase + g]);
                bf1[kb] = __float_as_uint(tx[(kb*8 + t4 + 4)*TAS + pbase + g]);
            }
            float e0 = bias_lo, e1 = bias_lo, e2 = bias_hi, e3 = bias_hi;
            float o0 = 0.f, o1 = 0.f, o2 = 0.f, o3 = 0.f;
#pragma unroll
            for (int kb = 0; kb < 8; kb += 2) {
                mma_tf32(e0,e1,e2,e3, af[kb][0],af[kb][1],af[kb][2],af[kb][3],
                         bf0[kb], bf1[kb]);
                mma_tf32(o0,o1,o2,o3, af[kb+1][0],af[kb+1][1],af[kb+1][2],af[kb+1][3],
                         bf0[kb+1], bf1[kb+1]);
            }
            float c0 = e0+o0, c1 = e1+o1, c2 = e2+o2, c3 = e3+o3;
            *(__half2*)(g_x2h + (size_t)(ob16+g)*PPOS   + p0 + pbase + 2*t4) = __floats2half2_rn(c0,c1);
            *(__half2*)(g_x2h + (size_t)(ob16+g+8)*PPOS + p0 + pbase + 2*t4) = __floats2half2_rn(c2,c3);
            st_s_lo += c0 + c1; st_q_lo = fmaf(c0,c0,fmaf(c1,c1,st_q_lo));
            st_s_hi += c2 + c3; st_q_hi = fmaf(c2,c2,fmaf(c3,c3,st_q_hi));
        }
        tile = next;
        buf ^= 1;
    }
#pragma unroll
    for (int d = 1; d < 4; d <<= 1) {
        st_s_lo += __shfl_xor_sync(0xFFFFFFFFu, st_s_lo, d);
        st_q_lo += __shfl_xor_sync(0xFFFFFFFFu, st_q_lo, d);
        st_s_hi += __shfl_xor_sync(0xFFFFFFFFu, st_s_hi, d);
        st_q_hi += __shfl_xor_sync(0xFFFFFFFFu, st_q_hi, d);
    }
    if (t4 == 0) {
        atomicAdd(&g_stats[ob16+g],        st_s_lo);
        atomicAdd(&g_stats[64 + ob16+g],   st_q_lo);
        atomicAdd(&g_stats[ob16+g+8],      st_s_hi);
        atomicAdd(&g_stats[64 + ob16+g+8], st_q_hi);
    }
}

// PERSISTENT layer3: warp = 32 outputs x 64 positions; fp16 staged, vectorized BN2.
__global__ __launch_bounds__(256,2) void mlp3_kernel(const float* __restrict__ w2,
                                                     const float* __restrict__ b2,
                                                     const float* __restrict__ g1,
                                                     const float* __restrict__ beta1)
{
    extern __shared__ char smraw[];
    float* sab  = (float*)smraw;                  // 128 floats (512B)
    char*  txh  = smraw + 512;                    // 64 rows x THB bytes fp16 stage
    float* txf  = (float*)(smraw + 512 + 64*THB); // 64 x TXS floats (mma tile)
    __shared__ int s_next;
    const int tid  = threadIdx.x;
    const int lane = tid & 31, wid = tid >> 5;
    const int ob = (wid & 3) * 32;
    const int ph = (wid >> 2) * 64;
    const int g  = lane >> 2;
    const int t4 = lane & 3;

    if (tid < 64) {
        const float invP = 1.0f / (float)PPOS;
        float mean = g_stats[tid]    * invP;
        float var  = g_stats[64+tid] * invP - mean*mean;
        float A = g1[tid] * rsqrtf(var + 1e-5f);
        sab[tid]    = A;
        sab[64+tid] = fmaf(-mean, A, beta1[tid]);
    }

    unsigned af[8][2][4];
#pragma unroll
    for (int kb = 0; kb < 8; ++kb)
#pragma unroll
        for (int mb = 0; mb < 2; ++mb) {
            int r = ob + mb*16;
            af[kb][mb][0] = __float_as_uint(w2[(r+g)*64   + kb*8 + t4]);
            af[kb][mb][1] = __float_as_uint(w2[(r+g+8)*64 + kb*8 + t4]);
            af[kb][mb][2] = __float_as_uint(w2[(r+g)*64   + kb*8 + t4 + 4]);
            af[kb][mb][3] = __float_as_uint(w2[(r+g+8)*64 + kb*8 + t4 + 4]);
        }
    const float bias0l = b2[ob+g],    bias0h = b2[ob+g+8];
    const float bias1l = b2[ob+16+g], bias1h = b2[ob+16+g+8];
    float st_s[4] = {0,0,0,0}, st_q[4] = {0,0,0,0};

    int tile = blockIdx.x;
#pragma unroll
    for (int k = 0; k < 4; ++k) {
        int i = tid + k*256;
        int c = i >> 4, ch = i & 15;
        cp_async16(txh + c*THB + ch*16, g_x2h + (size_t)c*PPOS + tile*128 + ch*8);
    }
    cp_commit(); cp_wait0();
    __syncthreads();

    while (tile < PPOS/128) {
        if (tid == 0) s_next = NPERS + atomicAdd(&g_ctr[1], 1);
        // BN2 affine + relu: fp16 stage -> f32 mma tile (2x half2 -> float4 per step)
#pragma unroll
        for (int k = 0; k < 8; ++k) {
            int i = tid + k*256;           // 0..2047
            int c = i >> 5, j8 = i & 31;
            float A = sab[c], Bv = sab[64+c];
            uint2 hv = *(uint2*)(txh + c*THB + j8*8);
            float2 f0 = __half22float2(*(__half2*)&hv.x);
            float2 f1 = __half22float2(*(__half2*)&hv.y);
            float4 r;
            r.x = fmaxf(fmaf(f0.x,A,Bv),0.f); r.y = fmaxf(fmaf(f0.y,A,Bv),0.f);
            r.z = fmaxf(fmaf(f1.x,A,Bv),0.f); r.w = fmaxf(fmaf(f1.y,A,Bv),0.f);
            *(float4*)(txf + c*TXS + j8*4) = r;
        }
        __syncthreads();                   // txf ready; txh consumed; s_next published
        const int next = s_next;

        if (next < PPOS/128) {             // overlap next fetch with ENTIRE mma
#pragma unroll
            for (int k = 0; k < 4; ++k) {
                int i = tid + k*256;
                int c = i >> 4, ch = i & 15;
                cp_async16(txh + c*THB + ch*16, g_x2h + (size_t)c*PPOS + next*128 + ch*8);
            }
        }
        cp_commit();

#pragma unroll
        for (int grp2 = 0; grp2 < 2; ++grp2) {
            float pmax[4] = {-3.4e38f,-3.4e38f,-3.4e38f,-3.4e38f};
            float pmin[4] = { 3.4e38f, 3.4e38f, 3.4e38f, 3.4e38f};
#pragma unroll
            for (int nbi = 0; nbi < 4; ++nbi) {
                const int pbase = ph + grp2*32 + nbi*8;
                unsigned bf0[8], bf1[8];
#pragma unroll
                for (int kb = 0; kb < 8; ++kb) {
                    bf0[kb] = __float_as_uint(txf[(kb*8 + t4)*TXS     + pbase + g]);
                    bf1[kb] = __float_as_uint(txf[(kb*8 + t4 + 4)*TXS + pbase + g]);
                }
                float a0 = bias0l, a1 = bias0l, a2 = bias0h, a3 = bias0h;
                float d0 = bias1l, d1 = bias1l, d2 = bias1h, d3 = bias1h;
#pragma unroll
                for (int kb = 0; kb < 8; ++kb) {
                    mma_tf32(a0,a1,a2,a3, af[kb][0][0],af[kb][0][1],af[kb][0][2],af[kb][0][3],
                             bf0[kb], bf1[kb]);
                    mma_tf32(d0,d1,d2,d3, af[kb][1][0],af[kb][1][1],af[kb][1][2],af[kb][1][3],
                             bf0[kb], bf1[kb]);
                }
                st_s[0] += a0 + a1; st_q[0] = fmaf(a0,a0,fmaf(a1,a1,st_q[0]));
                st_s[1] += a2 + a3; st_q[1] = fmaf(a2,a2,fmaf(a3,a3,st_q[1]));
                st_s[2] += d0 + d1; st_q[2] = fmaf(d0,d0,fmaf(d1,d1,st_q[2]));
                st_s[3] += d2 + d3; st_q[3] = fmaf(d2,d2,fmaf(d3,d3,st_q[3]));
                pmax[0] = fmaxf(pmax[0], fmaxf(a0,a1)); pmin[0] = fminf(pmin[0], fminf(a0,a1));
                pmax[1] = fmaxf(pmax[1], fmaxf(a2,a3)); pmin[1] = fminf(pmin[1], fminf(a2,a3));
                pmax[2] = fmaxf(pmax[2], fmaxf(d0,d1)); pmin[2] = fminf(pmin[2], fminf(d0,d1));
                pmax[3] = fmaxf(pmax[3], fmaxf(d2,d3)); pmin[3] = fminf(pmin[3], fminf(d2,d3));
            }
#pragma unroll
            for (int d = 1; d < 4; d <<= 1)
#pragma unroll
                for (int i = 0; i < 4; ++i) {
                    pmax[i] = fmaxf(pmax[i], __shfl_xor_sync(0xFFFFFFFFu, pmax[i], d));
                    pmin[i] = fminf(pmin[i], __shfl_xor_sync(0xFFFFFFFFu, pmin[i], d));
                }
            if (t4 == 0) {
                int gid = tile*4 + (ph >> 5) + grp2;
                int ch[4] = { ob+g, ob+g+8, ob+16+g, ob+16+g+8 };
#pragma unroll
                for (int i = 0; i < 4; ++i)
                    g_pool[ch[i]*NGRP + gid] = make_float2(pmax[i], pmin[i]);
            }
        }
        cp_wait0();
        __syncthreads();
        tile = next;
    }
#pragma unroll
    for (int d = 1; d < 4; d <<= 1)
#pragma unroll
        for (int i = 0; i < 4; ++i) {
            st_s[i] += __shfl_xor_sync(0xFFFFFFFFu, st_s[i], d);
            st_q[i] += __shfl_xor_sync(0xFFFFFFFFu, st_q[i], d);
        }
    if (t4 == 0) {
        int ch[4] = { ob+g, ob+g+8, ob+16+g, ob+16+g+8 };
#pragma unroll
        for (int i = 0; i < 4; ++i) {
            atomicAdd(&g_stats[128 + ch[i]], st_s[i]);
            atomicAdd(&g_stats[256 + ch[i]], st_q[i]);
        }
    }
}

// Final: inline BN3 fold + affine+relu on pooled max/min. One CTA per (b,o).
__global__ __launch_bounds__(256) void final_kernel(float* __restrict__ out,
                                                    const float* __restrict__ g2,
                                                    const float* __restrict__ beta2)
{
    __shared__ float sA, sB;
    const int o = blockIdx.x & 127;
    const int b = blockIdx.x >> 7;
    if (threadIdx.x == 0) {
        const float invP = 1.0f / (float)PPOS;
        float mean = g_stats[128+o] * invP;
        float var  = g_stats[256+o] * invP - mean*mean;
        float A = g2[o] * rsqrtf(var + 1e-5f);
        sA = A; sB = fmaf(-mean, A, beta2[o]);
    }
    __syncthreads();
    float A = sA, Bv = sB;
    int s = threadIdx.x * 2;
    float2 p0 = g_pool[o*NGRP + b*SS + s];
    float2 p1 = g_pool[o*NGRP + b*SS + s + 1];
    float v0 = (A >= 0.0f) ? p0.x : p0.y;
    float v1 = (A >= 0.0f) ? p1.x : p1.y;
    float2 r;
    r.x = fmaxf(fmaf(v0, A, Bv), 0.0f);
    r.y = fmaxf(fmaf(v1, A, Bv), 0.0f);
    *(float2*)(out + ((b*128 + o) << 9) + s) = r;
}

// ---------------- launch ----------------
extern "C" void kernel_launch(void* const* d_in, const int* in_sizes, int n_in,
                              void* d_out, int out_size)
{
    const float* xyz = (const float*)d_in[0];
    const float* pts = (const float*)d_in[1];
    const float* w0  = (const float*)d_in[2];
    const float* b0  = (const float*)d_in[3];
    const float* gm0 = (const float*)d_in[4];
    const float* be0 = (const float*)d_in[5];
    const float* w1  = (const float*)d_in[6];
    const float* b1  = (const float*)d_in[7];
    const float* gm1 = (const float*)d_in[8];
    const float* be1 = (const float*)d_in[9];
    const float* w2  = (const float*)d_in[10];
    const float* b2  = (const float*)d_in[11];
    const float* gm2 = (const float*)d_in[12];
    const float* be2 = (const float*)d_in[13];
    float* out = (float*)d_out;

    const int f12_smem  = 15872 + TAS*64*4;          // 83456
    const int mlp3_smem = 512 + 64*THB + TXS*64*4;   // 52736

    cudaFuncSetAttribute(fps_kernel,     cudaFuncAttributeMaxDynamicSharedMemorySize, 73728);
    cudaFuncSetAttribute(fused12_kernel, cudaFuncAttributeMaxDynamicSharedMemorySize, f12_smem);
    cudaFuncSetAttribute(mlp3_kernel,    cudaFuncAttributeMaxDynamicSharedMemorySize, mlp3_smem);

    fps_kernel<<<BB, 512, 73728>>>(xyz, out);
    group_kernel<<<(BB*SS)/8, 256>>>(xyz, pts);
    fused12_kernel<<<NPERS, 256, f12_smem>>>(w0, b0, gm0, be0, w1, b1);
    mlp3_kernel<<<NPERS, 256, mlp3_smem>>>(w2, b2, gm1, be1);
    final_kernel<<<BB*128, 256>>>(out + BB*3*SS, gm2, be2);
}